// round 1
// baseline (speedup 1.0000x reference)
#include <cuda_runtime.h>
#include <cstdint>

#define VOCAB 32000
#define BOS_ID 1
#define BSZ 8
#define SEQLEN 2048

// Per-row majority token, computed by hist_kernel, consumed by fill_kernel.
__device__ int g_pred[BSZ];

// ---------------------------------------------------------------------------
// Kernel 1: per-row histogram + argmax (ties -> lowest index), BOS fallback.
// One block per batch row. Dynamic smem: VOCAB ints = 128000 bytes (opt-in).
// ---------------------------------------------------------------------------
__global__ void hist_kernel(const int* __restrict__ ids) {
    extern __shared__ int counts[];
    __shared__ int sh_best;

    const int b = blockIdx.x;
    const int t = threadIdx.x;
    const int nt = blockDim.x;

    for (int i = t; i < VOCAB; i += nt) counts[i] = 0;
    if (t == 0) sh_best = 0;
    __syncthreads();

    const int* row = ids + b * SEQLEN;
    #pragma unroll 2
    for (int i = t; i < SEQLEN; i += nt) {
        int v = row[i];
        if (v != 0 && v != BOS_ID) atomicAdd(&counts[v], 1);
    }
    __syncthreads();

    // Packed key: (count << 15) | (0x7FFF - v).
    // Higher count wins; among equal counts, lower v wins (matches argmax tie rule).
    // count <= 2048 fits in 12 bits; v < 32000 fits in 15 bits. Packed < 2^27.
    int best = 0;
    for (int i = t; i < VOCAB; i += nt) {
        int packed = (counts[i] << 15) | (0x7FFF - i);
        if (packed > best) best = packed;
    }
    atomicMax(&sh_best, best);
    __syncthreads();

    if (t == 0) {
        int cnt = sh_best >> 15;
        int v   = 0x7FFF - (sh_best & 0x7FFF);
        g_pred[b] = (cnt > 0) ? v : BOS_ID;  // no valid tokens -> BOS
    }
}

// ---------------------------------------------------------------------------
// Kernel 2: stream 2.1 GB of logits. One float4 (STG.128) per thread.
// grid = (SEQLEN*VOCAB/4/256, BSZ). Row-within-vocab via modulo by 8000.
// ---------------------------------------------------------------------------
__global__ void __launch_bounds__(256) fill_kernel(float4* __restrict__ out) {
    const int ROW4 = VOCAB / 4;                       // 8000 float4 per (b,s) row
    const long long per_b = (long long)SEQLEN * ROW4; // 16,384,000 float4 per batch

    const int b = blockIdx.y;
    const long long i_in_b = (long long)blockIdx.x * blockDim.x + threadIdx.x;
    const int r = (int)(i_in_b % ROW4);               // float4 index within vocab row

    const int pred = g_pred[b];

    float4 val = make_float4(-6.0f, -6.0f, -6.0f, -6.0f);
    const int vb = r * 4;
    if (pred >= vb && pred < vb + 4) {
        reinterpret_cast<float*>(&val)[pred - vb] = 6.0f;
    }

    out[(long long)b * per_b + i_in_b] = val;
}

// ---------------------------------------------------------------------------
extern "C" void kernel_launch(void* const* d_in, const int* in_sizes, int n_in,
                              void* d_out, int out_size) {
    (void)in_sizes; (void)n_in; (void)out_size;
    const int* ids = (const int*)d_in[0];
    float4* out = (float4*)d_out;

    const int smem_bytes = VOCAB * (int)sizeof(int);  // 128000 bytes
    cudaFuncSetAttribute(hist_kernel,
                         cudaFuncAttributeMaxDynamicSharedMemorySize, smem_bytes);

    hist_kernel<<<BSZ, 1024, smem_bytes>>>(ids);

    // SEQLEN * VOCAB/4 = 16,384,000 float4 per batch row; / 256 threads = 64000 blocks
    dim3 grid((SEQLEN * (VOCAB / 4)) / 256, BSZ);
    fill_kernel<<<grid, 256>>>(out);
}